// round 4
// baseline (speedup 1.0000x reference)
#include <cuda_runtime.h>

// SSIM loss, fused streaming kernel — warp-independent strips, no block
// barriers in the main loop, packed f32x2 math (sm_103a FFMA2).
// 16x3x512x512 fp32 pred/target -> scalar 1 - mean(ssim_map).

#define IMG   512
#define PLANES 48
#define KW    11
#define KR    5
#define TW    128                 // block tile width (4 warps x 32 cols)
#define TH    64
#define NRB   7                   // 7*11 = 77 rows streamed >= TH+10
#define NTHREADS 128
#define GRIDX (IMG/TW)            // 4
#define GRIDY (IMG/TH)            // 8
#define NBLK  (GRIDX*GRIDY*PLANES)  // 1536
#define NPIXD ((double)PLANES * IMG * IMG)
#define WSW   44                  // per-warp staging width (42 used, padded)

typedef unsigned long long u64;

__device__ double       g_sum;
__device__ unsigned int g_cnt;

__device__ __forceinline__ u64 pk2(float x, float y) {
    u64 r; asm("mov.b64 %0, {%1, %2};" : "=l"(r) : "f"(x), "f"(y)); return r;
}
__device__ __forceinline__ void upk2(u64 v, float& x, float& y) {
    asm("mov.b64 {%0, %1}, %2;" : "=f"(x), "=f"(y) : "l"(v));
}
__device__ __forceinline__ u64 fma2(u64 a, u64 b, u64 c) {
    u64 d; asm("fma.rn.f32x2 %0, %1, %2, %3;" : "=l"(d) : "l"(a), "l"(b), "l"(c));
    return d;
}
__device__ __forceinline__ u64 mul2(u64 a, u64 b) {
    u64 d; asm("mul.rn.f32x2 %0, %1, %2;" : "=l"(d) : "l"(a), "l"(b));
    return d;
}

__global__ __launch_bounds__(NTHREADS, 4)
void ssim_kernel(const float* __restrict__ pred,
                 const float* __restrict__ targ,
                 float* __restrict__ out)
{
    constexpr float W[KW] = {
        0.00102838f, 0.00759876f, 0.03600077f, 0.10936069f, 0.21300554f,
        0.26601173f,
        0.21300554f, 0.10936069f, 0.03600077f, 0.00759876f, 0.00102838f
    };
    constexpr float C1 = 0.0001f;
    constexpr float C2 = 0.0009f;

    __shared__ float2 sb[4][2][WSW];   // per-warp double-buffered (x,y) rows
    __shared__ float  wsum[4];

    const int t = threadIdx.x;
    const int w = t >> 5;
    const int l = t & 31;
    const int x0 = blockIdx.x * TW;
    const int y0 = blockIdx.y * TH;
    const float* __restrict__ xin = pred + (size_t)blockIdx.z * IMG * IMG;
    const float* __restrict__ yin = targ + (size_t)blockIdx.z * IMG * IMG;

    const int  base = x0 + w * 32;          // warp strip start column
    const int  gxa  = base - KR + l;        // staging idx l
    const int  gxb  = base + 27 + l;        // staging idx 32+l (lanes 0..9)
    const bool tail = (l < 10);
    // warp-uniform: entire 42-col x 77-row window strictly inside the image?
    const bool safe = (base >= KR) && (base + 37 <= IMG) &&
                      (y0 >= KR) && (y0 + 72 < IMG);

    auto ldrow = [&](int j, float& ax0, float& ax1, float& ay0, float& ay1) {
        const int gy = y0 - KR + j;
        if (safe) {                          // uniform branch, no predicates
            const long b = (long)gy * IMG;
            ax0 = xin[b + gxa];
            ay0 = yin[b + gxa];
            if (tail) { ax1 = xin[b + gxb]; ay1 = yin[b + gxb]; }
            else      { ax1 = 0.f; ay1 = 0.f; }
        } else {
            const bool rok = (gy >= 0) && (gy < IMG);
            const bool ok0 = rok && (gxa >= 0) && (gxa < IMG);
            const bool ok1 = rok && tail && (gxb < IMG);
            const long b = (long)gy * IMG;
            ax0 = ok0 ? xin[b + gxa] : 0.0f;
            ay0 = ok0 ? yin[b + gxa] : 0.0f;
            ax1 = ok1 ? xin[b + gxb] : 0.0f;
            ay1 = ok1 ? yin[b + gxb] : 0.0f;
        }
    };

    u64 WW[KW];
    #pragma unroll
    for (int k = 0; k < KW; ++k) WW[k] = pk2(W[k], W[k]);
    const u64 NEG1 = pk2(-1.0f, -1.0f);
    const u64 Z64  = 0ull;

    u64 aMU[11], aSQ[11];
    float aXY[11];
    #pragma unroll
    for (int s = 0; s < 11; ++s) { aMU[s] = Z64; aSQ[s] = Z64; aXY[s] = 0.f; }

    float tsum = 0.0f;

    // preload + stage row 0
    {
        float ax0, ax1, ay0, ay1;
        ldrow(0, ax0, ax1, ay0, ay1);
        sb[w][0][l] = make_float2(ax0, ay0);
        if (tail) sb[w][0][32 + l] = make_float2(ax1, ay1);
    }
    __syncwarp();

    for (int jb = 0; jb < NRB; ++jb) {
        #pragma unroll
        for (int u = 0; u < 11; ++u) {
            const int j = jb * 11 + u;

            // prefetch next row (overlaps compute)
            float nx0, nx1, ny0, ny1;
            ldrow(j + 1, nx0, nx1, ny0, ny1);

            // ---- horizontal blur, packed, LDS.64 per tap ----
            const u64* s = (const u64*)sb[w][j & 1];
            u64 hmu = Z64, hsq = Z64;
            float hxy = 0.f;
            #pragma unroll
            for (int k = 0; k < KW; ++k) {
                const u64 p  = s[l + k];
                const u64 pp = mul2(p, p);
                hmu = fma2(WW[k], p,  hmu);
                hsq = fma2(WW[k], pp, hsq);
                float a, b; upk2(p, a, b);
                hxy = fmaf(W[k], a * b, hxy);
            }

            // ---- vertical ring update (slot indices are literals) ----
            #pragma unroll
            for (int p = 0; p < KW; ++p) {
                const int ss = (u - p + 11) % 11;
                aMU[ss] = fma2(WW[p], hmu, aMU[ss]);
                aSQ[ss] = fma2(WW[p], hsq, aSQ[ss]);
                aXY[ss] = fmaf(W[p], hxy, aXY[ss]);
            }

            // ---- finalize output row o = j-10, then reset its slot ----
            {
                const int so = (u + 1) % 11;
                const int o  = j - (KW - 1);
                if (o >= 0 && o < TH) {
                    const u64 mu  = aMU[so];
                    const u64 mu2 = mul2(mu, mu);             // (mux^2, muy^2)
                    const u64 sg  = fma2(mu2, NEG1, aSQ[so]); // (sgx, sgy)
                    float mux, muy, m2x, m2y, sgx, sgy;
                    upk2(mu,  mux, muy);
                    upk2(mu2, m2x, m2y);
                    upk2(sg,  sgx, sgy);
                    const float muxy = mux * muy;
                    const float sgxy = aXY[so] - muxy;
                    const float num  = (2.0f * muxy + C1) * (2.0f * sgxy + C2);
                    const float den  = (m2x + m2y + C1) * (sgx + sgy + C2);
                    tsum += __fdividef(num, den);
                }
                aMU[so] = Z64; aSQ[so] = Z64; aXY[so] = 0.f;
            }

            // stage prefetched row j+1 (other buffer). Safe: overwrites data
            // last read in iter j-1, fenced by that iter's __syncwarp.
            const int nb = (j + 1) & 1;
            sb[w][nb][l] = make_float2(nx0, ny0);
            if (tail) sb[w][nb][32 + l] = make_float2(nx1, ny1);
            __syncwarp();
        }
    }

    // ---- reduction: warp -> block -> global ----
    #pragma unroll
    for (int off = 16; off > 0; off >>= 1)
        tsum += __shfl_down_sync(0xffffffffu, tsum, off);
    if (l == 0) wsum[w] = tsum;
    __syncthreads();

    if (t == 0) {
        const double bs = (double)wsum[0] + (double)wsum[1]
                        + (double)wsum[2] + (double)wsum[3];
        atomicAdd(&g_sum, bs);
        __threadfence();
        const unsigned r = atomicAdd(&g_cnt, 1u);
        if (r == NBLK - 1u) {
            const double sall = g_sum;
            out[0] = (float)(1.0 - sall / NPIXD);
            g_sum = 0.0;
            __threadfence();
            g_cnt = 0u;
        }
    }
}

extern "C" void kernel_launch(void* const* d_in, const int* in_sizes, int n_in,
                              void* d_out, int out_size)
{
    const float* pred = (const float*)d_in[0];
    const float* targ = (const float*)d_in[1];
    float* out = (float*)d_out;

    dim3 grid(GRIDX, GRIDY, PLANES);   // 4 x 8 x 48 = 1536 blocks
    ssim_kernel<<<grid, NTHREADS>>>(pred, targ, out);
}

// round 5
// speedup vs baseline: 1.7753x; 1.7753x over previous
#include <cuda_runtime.h>

// SSIM loss, fused streaming kernel (R3 structure + 4-deep row ring,
// barrier every 2 rows, 2-row-deep LDG prefetch). sm_103a f32x2 math.
// 16x3x512x512 fp32 pred/target -> scalar 1 - mean(ssim_map).

#define IMG   512
#define PLANES 48
#define KW    11
#define KR    5
#define TW    128
#define TH    64
#define NRB   7                  // 7*11 = 77 rows streamed (j = 0..76)
#define NROWS 77
#define SW    (TW + 2*KR)        // 138
#define NTHREADS 128
#define GRIDX (IMG/TW)           // 4
#define GRIDY (IMG/TH)           // 8
#define NBLK  (GRIDX*GRIDY*PLANES)  // 1536
#define NPIXD ((double)PLANES * IMG * IMG)

typedef unsigned long long u64;

__device__ double       g_sum;
__device__ unsigned int g_cnt;

__device__ __forceinline__ u64 pk2(float x, float y) {
    u64 r; asm("mov.b64 %0, {%1, %2};" : "=l"(r) : "f"(x), "f"(y)); return r;
}
__device__ __forceinline__ void upk2(u64 v, float& x, float& y) {
    asm("mov.b64 {%0, %1}, %2;" : "=f"(x), "=f"(y) : "l"(v));
}
__device__ __forceinline__ u64 fma2(u64 a, u64 b, u64 c) {
    u64 d; asm("fma.rn.f32x2 %0, %1, %2, %3;" : "=l"(d) : "l"(a), "l"(b), "l"(c));
    return d;
}
__device__ __forceinline__ u64 mul2(u64 a, u64 b) {
    u64 d; asm("mul.rn.f32x2 %0, %1, %2;" : "=l"(d) : "l"(a), "l"(b));
    return d;
}

__global__ __launch_bounds__(NTHREADS, 4)
void ssim_kernel(const float* __restrict__ pred,
                 const float* __restrict__ targ,
                 float* __restrict__ out)
{
    constexpr float W[KW] = {
        0.00102838f, 0.00759876f, 0.03600077f, 0.10936069f, 0.21300554f,
        0.26601173f,
        0.21300554f, 0.10936069f, 0.03600077f, 0.00759876f, 0.00102838f
    };
    constexpr float C1 = 0.0001f;
    constexpr float C2 = 0.0009f;

    __shared__ float2 sb[4][SW];      // 4-deep ring of interleaved (x,y) rows
    __shared__ float  wsum[4];

    const int t  = threadIdx.x;
    const int x0 = blockIdx.x * TW;
    const int y0 = blockIdx.y * TH;
    const float* __restrict__ xin = pred + (size_t)blockIdx.z * IMG * IMG;
    const float* __restrict__ yin = targ + (size_t)blockIdx.z * IMG * IMG;

    const int  gx0  = x0 - KR + t;
    const int  gx1  = gx0 + TW;
    const bool tail = (t < SW - TW);

    // load one padded row into 4 registers (zeros outside image / past NROWS)
    auto ldrow = [&](int r, float& ax0, float& ax1, float& ay0, float& ay1) {
        const int  gy  = y0 - KR + r;
        const bool rok = (r < NROWS) && (gy >= 0) && (gy < IMG);
        const bool ok0 = rok && (gx0 >= 0) && (gx0 < IMG);
        const bool ok1 = rok && tail && (gx1 < IMG);
        const long b = (long)gy * IMG;
        ax0 = ok0 ? xin[b + gx0] : 0.0f;
        ay0 = ok0 ? yin[b + gx0] : 0.0f;
        ax1 = ok1 ? xin[b + gx1] : 0.0f;
        ay1 = ok1 ? yin[b + gx1] : 0.0f;
    };
    auto strow = [&](int r, float ax0, float ax1, float ay0, float ay1) {
        float2* buf = sb[r & 3];
        buf[t] = make_float2(ax0, ay0);
        if (tail) buf[TW + t] = make_float2(ax1, ay1);
    };

    // 6 distinct packed weights (Gaussian symmetry) — halves weight regs
    u64 WW[6];
    #pragma unroll
    for (int k = 0; k < 6; ++k) WW[k] = pk2(W[k], W[k]);
    const u64 NEG1 = pk2(-1.0f, -1.0f);
    const u64 Z64  = 0ull;

    u64 aMU[11], aSQ[11];
    float aXY[11];
    #pragma unroll
    for (int s = 0; s < 11; ++s) { aMU[s] = Z64; aSQ[s] = Z64; aXY[s] = 0.f; }

    float tsum = 0.0f;

    // ---- prologue: stage rows 0..3, prefetch rows 4,5 ----
    {
        float a0, a1, b0, b1;
        #pragma unroll
        for (int r = 0; r < 4; ++r) {
            ldrow(r, a0, a1, b0, b1);
            strow(r, a0, a1, b0, b1);
        }
    }
    float pA0, pA1, pB0, pB1;   // prefetched row (even slot)
    float qA0, qA1, qB0, qB1;   // prefetched row (odd slot)
    ldrow(4, pA0, pA1, pB0, pB1);
    ldrow(5, qA0, qA1, qB0, qB1);
    __syncthreads();

    for (int jb = 0; jb < NRB; ++jb) {
        #pragma unroll
        for (int u = 0; u < 11; ++u) {
            const int j = jb * 11 + u;

            // ---- horizontal blur of row j, packed ----
            const u64* s = (const u64*)sb[j & 3];
            u64 hmu = Z64, hsq = Z64;
            float hxy = 0.f;
            #pragma unroll
            for (int k = 0; k < KW; ++k) {
                const int kw = (k < 6) ? k : 10 - k;   // literal
                const u64 p  = s[t + k];
                const u64 pp = mul2(p, p);
                hmu = fma2(WW[kw], p,  hmu);
                hsq = fma2(WW[kw], pp, hsq);
                float a, b; upk2(p, a, b);
                hxy = fmaf(W[k], a * b, hxy);
            }

            // ---- vertical ring update (slot indices literal) ----
            #pragma unroll
            for (int p = 0; p < KW; ++p) {
                const int ss = (u - p + 11) % 11;
                const int pw = (p < 6) ? p : 10 - p;   // literal
                aMU[ss] = fma2(WW[pw], hmu, aMU[ss]);
                aSQ[ss] = fma2(WW[pw], hsq, aSQ[ss]);
                aXY[ss] = fmaf(W[p], hxy, aXY[ss]);
            }

            // ---- finalize output row o = j-10 ----
            {
                const int so = (u + 1) % 11;
                const int o  = j - (KW - 1);
                if (o >= 0 && o < TH) {
                    const u64 mu  = aMU[so];
                    const u64 mu2 = mul2(mu, mu);
                    const u64 sg  = fma2(mu2, NEG1, aSQ[so]);
                    float mux, muy, m2x, m2y, sgx, sgy;
                    upk2(mu,  mux, muy);
                    upk2(mu2, m2x, m2y);
                    upk2(sg,  sgx, sgy);
                    const float muxy = mux * muy;
                    const float sgxy = aXY[so] - muxy;
                    const float num  = (2.0f * muxy + C1) * (2.0f * sgxy + C2);
                    const float den  = (m2x + m2y + C1) * (sgx + sgy + C2);
                    tsum += __fdividef(num, den);
                }
                aMU[so] = Z64; aSQ[so] = Z64; aXY[so] = 0.f;
            }

            // ---- every 2nd row: barrier, stage 2 prefetched rows, refetch ----
            // Rows j+3, j+4 overwrite rows j-1, j (both fully consumed by the
            // barrier below); their stores become visible to readers (rows
            // j+3 at iter j+3, j+4 at iter j+4) via the barrier at j+2.
            if (j & 1) {
                __syncthreads();
                strow(j + 3, pA0, pA1, pB0, pB1);
                strow(j + 4, qA0, qA1, qB0, qB1);
                ldrow(j + 5, pA0, pA1, pB0, pB1);
                ldrow(j + 6, qA0, qA1, qB0, qB1);
            }
        }
    }

    // ---- reduction: warp -> block -> global ----
    #pragma unroll
    for (int off = 16; off > 0; off >>= 1)
        tsum += __shfl_down_sync(0xffffffffu, tsum, off);
    if ((t & 31) == 0) wsum[t >> 5] = tsum;
    __syncthreads();

    if (t == 0) {
        const double bs = (double)wsum[0] + (double)wsum[1]
                        + (double)wsum[2] + (double)wsum[3];
        atomicAdd(&g_sum, bs);
        __threadfence();
        const unsigned r = atomicAdd(&g_cnt, 1u);
        if (r == NBLK - 1u) {
            const double sall = g_sum;
            out[0] = (float)(1.0 - sall / NPIXD);
            g_sum = 0.0;
            __threadfence();
            g_cnt = 0u;
        }
    }
}

extern "C" void kernel_launch(void* const* d_in, const int* in_sizes, int n_in,
                              void* d_out, int out_size)
{
    const float* pred = (const float*)d_in[0];
    const float* targ = (const float*)d_in[1];
    float* out = (float*)d_out;

    dim3 grid(GRIDX, GRIDY, PLANES);   // 4 x 8 x 48 = 1536 blocks
    ssim_kernel<<<grid, NTHREADS>>>(pred, targ, out);
}

// round 6
// speedup vs baseline: 2.1832x; 1.2298x over previous
#include <cuda_runtime.h>

// SSIM loss, fused streaming kernel — (s,d)=(x+y,x-y) transform reduces the
// problem to 4 convolved fields packed as two f32x2 rings. R3 double-buffer
// staging (block-wide coalesced, 1 barrier/row). sm_103a packed math.
// 16x3x512x512 fp32 pred/target -> scalar 1 - mean(ssim_map).

#define IMG   512
#define PLANES 48
#define KW    11
#define KR    5
#define TW    128
#define TH    64
#define NRB   7                  // 7*11 = 77 rows streamed >= TH+10
#define SW    (TW + 2*KR)        // 138
#define NTHREADS 128
#define GRIDX (IMG/TW)           // 4
#define GRIDY (IMG/TH)           // 8
#define NBLK  (GRIDX*GRIDY*PLANES)  // 1536
#define NPIXD ((double)PLANES * IMG * IMG)

typedef unsigned long long u64;

__device__ double       g_sum;
__device__ unsigned int g_cnt;

__device__ __forceinline__ u64 pk2(float x, float y) {
    u64 r; asm("mov.b64 %0, {%1, %2};" : "=l"(r) : "f"(x), "f"(y)); return r;
}
__device__ __forceinline__ void upk2(u64 v, float& x, float& y) {
    asm("mov.b64 {%0, %1}, %2;" : "=f"(x), "=f"(y) : "l"(v));
}
__device__ __forceinline__ u64 fma2(u64 a, u64 b, u64 c) {
    u64 d; asm("fma.rn.f32x2 %0, %1, %2, %3;" : "=l"(d) : "l"(a), "l"(b), "l"(c));
    return d;
}
__device__ __forceinline__ u64 mul2(u64 a, u64 b) {
    u64 d; asm("mul.rn.f32x2 %0, %1, %2;" : "=l"(d) : "l"(a), "l"(b));
    return d;
}

__global__ __launch_bounds__(NTHREADS, 5)
void ssim_kernel(const float* __restrict__ pred,
                 const float* __restrict__ targ,
                 float* __restrict__ out)
{
    constexpr float W[KW] = {
        0.00102838f, 0.00759876f, 0.03600077f, 0.10936069f, 0.21300554f,
        0.26601173f,
        0.21300554f, 0.10936069f, 0.03600077f, 0.00759876f, 0.00102838f
    };
    constexpr float C1 = 0.0001f;
    constexpr float C2 = 0.0009f;

    __shared__ float2 sb[2][SW];      // interleaved (s, d) staging rows
    __shared__ float  wsum[4];

    const int t  = threadIdx.x;
    const int x0 = blockIdx.x * TW;
    const int y0 = blockIdx.y * TH;
    const float* __restrict__ xin = pred + (size_t)blockIdx.z * IMG * IMG;
    const float* __restrict__ yin = targ + (size_t)blockIdx.z * IMG * IMG;

    const int  gx0  = x0 - KR + t;
    const int  gx1  = gx0 + TW;
    const bool tail = (t < SW - TW);

    // load one padded row; return (s,d) = (x+y, x-y) pairs
    auto ldrow = [&](int j, float& s0, float& d0, float& s1, float& d1) {
        const int  gy  = y0 - KR + j;
        const bool rok = (gy >= 0) && (gy < IMG);
        const bool ok0 = rok && (gx0 >= 0) && (gx0 < IMG);
        const bool ok1 = rok && tail && (gx1 < IMG);
        const long b = (long)gy * IMG;
        const float ax0 = ok0 ? xin[b + gx0] : 0.0f;
        const float ay0 = ok0 ? yin[b + gx0] : 0.0f;
        const float ax1 = ok1 ? xin[b + gx1] : 0.0f;
        const float ay1 = ok1 ? yin[b + gx1] : 0.0f;
        s0 = ax0 + ay0;  d0 = ax0 - ay0;
        s1 = ax1 + ay1;  d1 = ax1 - ay1;
    };

    // 6 distinct packed weights (Gaussian symmetry)
    u64 WW[6];
    #pragma unroll
    for (int k = 0; k < 6; ++k) WW[k] = pk2(W[k], W[k]);
    const u64 NEG1 = pk2(-1.0f, -1.0f);
    const u64 Z64  = 0ull;

    // ring accumulators: packed (mu_s, mu_d) and (E[s^2], E[d^2])
    u64 aMU[11], aSQ[11];
    #pragma unroll
    for (int s = 0; s < 11; ++s) { aMU[s] = Z64; aSQ[s] = Z64; }

    float tsum = 0.0f;

    // preload + stage row 0
    {
        float s0, d0, s1, d1;
        ldrow(0, s0, d0, s1, d1);
        sb[0][t] = make_float2(s0, d0);
        if (tail) sb[0][TW + t] = make_float2(s1, d1);
    }
    __syncthreads();

    for (int jb = 0; jb < NRB; ++jb) {
        #pragma unroll
        for (int u = 0; u < 11; ++u) {
            const int j = jb * 11 + u;

            // prefetch next row (overlaps compute)
            float ns0, nd0, ns1, nd1;
            ldrow(j + 1, ns0, nd0, ns1, nd1);

            // ---- horizontal blur: 3 packed ops per tap ----
            const u64* s = (const u64*)sb[j & 1];
            u64 hmu = Z64, hsq = Z64;
            #pragma unroll
            for (int k = 0; k < KW; ++k) {
                const int kw = (k < 6) ? k : 10 - k;    // literal
                const u64 p  = s[t + k];                // (s, d) LDS.64
                const u64 pp = mul2(p, p);              // (s^2, d^2)
                hmu = fma2(WW[kw], p,  hmu);
                hsq = fma2(WW[kw], pp, hsq);
            }

            // ---- vertical ring update: 2 packed ops per tap ----
            #pragma unroll
            for (int p = 0; p < KW; ++p) {
                const int ss = (u - p + 11) % 11;       // literal
                const int pw = (p < 6) ? p : 10 - p;    // literal
                aMU[ss] = fma2(WW[pw], hmu, aMU[ss]);
                aSQ[ss] = fma2(WW[pw], hsq, aSQ[ss]);
            }

            // ---- finalize output row o = j-10, reset slot ----
            {
                const int so = (u + 1) % 11;
                const int o  = j - (KW - 1);
                if (o >= 0 && o < TH) {
                    const u64 mu  = aMU[so];
                    const u64 mu2 = mul2(mu, mu);            // (mus^2, mud^2)
                    const u64 sg  = fma2(mu2, NEG1, aSQ[so]); // (sig_s, sig_d)
                    float g0, g1, v0, v1;
                    upk2(mu2, g0, g1);
                    upk2(sg,  v0, v1);
                    // 2*mu_xy = (g0-g1)/2 ; mu_x^2+mu_y^2 = (g0+g1)/2
                    // 2*sg_xy = (v0-v1)/2 ; sg_x+sg_y     = (v0+v1)/2
                    const float num = (0.5f*(g0 - g1) + C1) * (0.5f*(v0 - v1) + C2);
                    const float den = (0.5f*(g0 + g1) + C1) * (0.5f*(v0 + v1) + C2);
                    tsum += __fdividef(num, den);
                }
                aMU[so] = Z64; aSQ[so] = Z64;
            }

            // stage prefetched row j+1 into the other buffer (overwrites data
            // last read in iter j-1, fenced by that iteration's barrier)
            const int nb = (j + 1) & 1;
            sb[nb][t] = make_float2(ns0, nd0);
            if (tail) sb[nb][TW + t] = make_float2(ns1, nd1);
            __syncthreads();
        }
    }

    // ---- reduction: warp -> block -> global ----
    #pragma unroll
    for (int off = 16; off > 0; off >>= 1)
        tsum += __shfl_down_sync(0xffffffffu, tsum, off);
    if ((t & 31) == 0) wsum[t >> 5] = tsum;
    __syncthreads();

    if (t == 0) {
        const double bs = (double)wsum[0] + (double)wsum[1]
                        + (double)wsum[2] + (double)wsum[3];
        atomicAdd(&g_sum, bs);
        __threadfence();
        const unsigned r = atomicAdd(&g_cnt, 1u);
        if (r == NBLK - 1u) {
            const double sall = g_sum;
            out[0] = (float)(1.0 - sall / NPIXD);
            g_sum = 0.0;
            __threadfence();
            g_cnt = 0u;
        }
    }
}

extern "C" void kernel_launch(void* const* d_in, const int* in_sizes, int n_in,
                              void* d_out, int out_size)
{
    const float* pred = (const float*)d_in[0];
    const float* targ = (const float*)d_in[1];
    float* out = (float*)d_out;

    dim3 grid(GRIDX, GRIDY, PLANES);   // 4 x 8 x 48 = 1536 blocks
    ssim_kernel<<<grid, NTHREADS>>>(pred, targ, out);
}